// round 5
// baseline (speedup 1.0000x reference)
#include <cuda_runtime.h>
#include <cstdint>
#include <math.h>

// NaiveFourierKANLayer via warp-level bf16 mma.sync, 3-term hi/lo split.
// R5: B pre-converted to bf16 hi/lo in smem-tile layout (cp.async fill),
//     term-grouped MMA ordering, profile-dealiasing pad kernel.

#define NI 256
#define NG 300
#define NO 256
#define SPLITK 8
#define IPC (NI/SPLITK)      // 32 i per CTA
#define NGC 10               // 32-g chunks per i (chunk 9 zero-padded)
#define NSTAGE (IPC*NGC)     // 320

#define RSB 144              // smem row pitch bytes -> conflict-free ldmatrix
#define A_HI 0
#define A_LO 18432
#define B_HI 36864
#define B_LO 55296
#define STAGE_BYTES 73728
#define DYN_SMEM (2*STAGE_BYTES)   // 147456

__device__ float g_scratch[SPLITK * 1024 * 256];        // 8 MB split-K partials
// B2[h][j][i][k320] bf16 stored as u32 pairs: [2][256][256][320] u32 = 160 MB
__device__ uint32_t g_B2[2u * 256u * 256u * 320u];

// ---------------- helpers ----------------
__device__ __forceinline__ uint32_t smem_u32(const void* p) {
    uint32_t a;
    asm("{ .reg .u64 t; cvta.to.shared.u64 t, %1; cvt.u32.u64 %0, t; }" : "=r"(a) : "l"(p));
    return a;
}
// pack2(a,b): low bf16 = a (even k), high bf16 = b (odd k)
__device__ __forceinline__ uint32_t pack2(float a, float b) {
    uint32_t r;
    asm("cvt.rn.bf16x2.f32 %0, %2, %1;" : "=r"(r) : "f"(a), "f"(b));
    return r;
}
__device__ __forceinline__ float lo_f(uint32_t p) { return __uint_as_float(p << 16); }
__device__ __forceinline__ float hi_f(uint32_t p) { return __uint_as_float(p & 0xFFFF0000u); }

#define LDSM4(r0,r1,r2,r3,addr)                                                  \
    asm volatile("ldmatrix.sync.aligned.m8n8.x4.shared.b16 {%0,%1,%2,%3}, [%4];" \
        : "=r"(r0), "=r"(r1), "=r"(r2), "=r"(r3) : "r"(addr))

#define MMA(d,a,b0,b1)                                                        \
    asm volatile("mma.sync.aligned.m16n8k16.row.col.f32.bf16.bf16.f32 "       \
        "{%0,%1,%2,%3},{%4,%5,%6,%7},{%8,%9},{%0,%1,%2,%3};"                  \
        : "+f"((d)[0]), "+f"((d)[1]), "+f"((d)[2]), "+f"((d)[3])              \
        : "r"((a)[0]), "r"((a)[1]), "r"((a)[2]), "r"((a)[3]), "r"(b0), "r"(b1))

#define CP16(dst,src) \
    asm volatile("cp.async.cg.shared.global [%0], [%1], 16;" :: "r"(dst), "l"(src))
#define CP_COMMIT() asm volatile("cp.async.commit_group;" ::: "memory")
#define CP_WAIT0()  asm volatile("cp.async.wait_group 0;" ::: "memory")

extern __shared__ char dsmem[];

// ---------------- B pre-conversion: fc fp32 -> bf16 hi/lo, tiled ----------------
__global__ void __launch_bounds__(512, 2)
fkan_conv(const float* __restrict__ fc)
{
    const int idx = blockIdx.x * 512 + threadIdx.x;     // 20,971,520 threads
    const int kp  = idx & 31;                           // k-pair within 64-k chunk
    const int rest = idx >> 5;
    const int gc  = rest % NGC;
    const int i   = (rest / NGC) & 255;
    const int j   = rest / (NGC * 256);                 // 0..255

    const int t  = kp >> 4;                             // 0 = cos, 1 = sin
    const int g0 = gc * 32 + ((2 * kp) & 31);
    const float* src = fc + ((size_t)(t * NO + j) * NI + i) * NG;
    const float v0 = (g0     < NG) ? src[g0]     : 0.f;
    const float v1 = (g0 + 1 < NG) ? src[g0 + 1] : 0.f;

    const uint32_t hp = pack2(v0, v1);
    const uint32_t lp = pack2(v0 - lo_f(hp), v1 - hi_f(hp));

    const uint32_t base = (((uint32_t)j * 256u + (uint32_t)i) * 320u) + (uint32_t)gc * 32u + (uint32_t)kp;
    g_B2[base] = hp;
    g_B2[base + 256u * 256u * 320u] = lp;
}

// ---------------- main MMA kernel ----------------
__global__ void __launch_bounds__(256, 1)
fkan_hmma(const float* __restrict__ x)
{
    const int tid  = threadIdx.x;
    const int lane = tid & 31;
    const int w    = tid >> 5;
    const int ks = blockIdx.x;            // split-K slice (i block)
    const int m0 = blockIdx.y * 128;      // batch-row tile
    const int n0 = blockIdx.z * 128;      // output-col tile

    const uint32_t smb = smem_u32(dsmem);

    // A producer map
    const int rr = tid >> 1, q = tid & 1;
    // B cp.async map: one (h, j) row per thread, 8 x 16B chunks
    const int bh_ = tid >> 7;             // 0 = hi, 1 = lo
    const int bj  = tid & 127;
    const uint32_t* browbase = g_B2 + ((uint32_t)bh_ * 256u + (uint32_t)(n0 + bj)) * 256u * 320u;
    const uint32_t bdst = smb + (uint32_t)(bh_ ? B_LO : B_HI) + (uint32_t)bj * RSB;

    // mma maps: 8 warps = 2(M) x 4(N); warp tile 64x32
    const int wm = w & 1, wn = w >> 1;
    const uint32_t aoff = (uint32_t)(wm*64 + (lane & 7) + ((lane >> 3) & 1)*8) * RSB
                        + (uint32_t)(lane >> 4) * 16;
    const uint32_t boff = (uint32_t)(wn*32 + (lane & 7) + (lane >> 4)*8) * RSB
                        + (uint32_t)((lane >> 3) & 1) * 16;

    float acc[4][4][4];
    #pragma unroll
    for (int a = 0; a < 4; ++a)
        #pragma unroll
        for (int b = 0; b < 4; ++b)
            #pragma unroll
            for (int c = 0; c < 4; ++c) acc[a][b][c] = 0.f;

    const float* xcol = x + (size_t)(m0 + rr) * NI + ks * IPC;

    // issue B copies for stage 0
    {
        const uint32_t* src = browbase + (uint32_t)(ks * IPC) * 320u;   // i = ks*IPC, gc=0
        const uint32_t d0 = bdst;   // stage buffer 0
        #pragma unroll
        for (int c = 0; c < 8; ++c) CP16(d0 + c * 16, src + c * 4);
        CP_COMMIT();
    }

    int it = 0;
    for (int ii = 0; ii < IPC; ++ii) {
        const float t = xcol[ii];
        float s1, c1;
        sincosf(t, &s1, &c1);
        const float c2 = fmaf(c1, c1, -(s1*s1)), s2 = 2.f*c1*s1;
        const float c4 = fmaf(c2, c2, -(s2*s2)), s4 = 2.f*c2*s2;
        const float c8 = fmaf(c4, c4, -(s4*s4)), s8 = 2.f*c4*s4;
        const float c16 = fmaf(c8, c8, -(s8*s8)), s16 = 2.f*c8*s8;
        float cc, ss;
        if (q) { cc = fmaf(c1, c16, -(s1*s16)); ss = fmaf(s1, c16, c1*s16); }
        else   { cc = c1; ss = s1; }

        for (int gc = 0; gc < NGC; ++gc, ++it) {
            char* sm = dsmem + (it & 1) * STAGE_BYTES;

            // ---- generate + STS A: 8 adjacent-g pairs; cos at k=gl, sin k=32+gl ----
            #pragma unroll
            for (int m = 0; m < 8; ++m) {
                const int gl = q*16 + 2*m;
                const int gg = gc*32 + gl;
                float ce = cc, se = ss;
                float co = fmaf(cc, c1, -(ss*s1));
                float so = fmaf(ss, c1,  cc*s1);
                if (gg     >= NG) { ce = 0.f; se = 0.f; }
                if (gg + 1 >= NG) { co = 0.f; so = 0.f; }
                const uint32_t chp = pack2(ce, co);
                const uint32_t clp = pack2(ce - lo_f(chp), co - hi_f(chp));
                const uint32_t shp = pack2(se, so);
                const uint32_t slp = pack2(se - lo_f(shp), so - hi_f(shp));
                const uint32_t offc = (uint32_t)rr * RSB + (uint32_t)gl * 2;
                *(uint32_t*)(sm + A_HI + offc)      = chp;
                *(uint32_t*)(sm + A_LO + offc)      = clp;
                *(uint32_t*)(sm + A_HI + offc + 64) = shp;
                *(uint32_t*)(sm + A_LO + offc + 64) = slp;
                const float nc = fmaf(cc, c2, -(ss*s2));
                ss = fmaf(ss, c2, cc*s2); cc = nc;
            }
            { const float nc = fmaf(cc, c16, -(ss*s16));
              ss = fmaf(ss, c16, cc*s16); cc = nc; }

            CP_WAIT0();              // B(it) landed
            __syncthreads();         // all MMA(it-1) reads + A(it) stores done

            // ---- issue B copies for stage it+1 (overlaps with MMA below) ----
            if (it + 1 < NSTAGE) {
                const int nit = it + 1;
                const int nii = nit / NGC, ngc2 = nit % NGC;
                const uint32_t* src = browbase + (uint32_t)(ks * IPC + nii) * 320u
                                    + (uint32_t)ngc2 * 32u;
                const uint32_t d0 = bdst + (uint32_t)((nit & 1) * STAGE_BYTES);
                #pragma unroll
                for (int c = 0; c < 8; ++c) CP16(d0 + c * 16, src + c * 4);
                CP_COMMIT();
            }

            // ---- consume: 4 K-steps; term-grouped MMA for ILP ----
            const uint32_t pA = smb + (uint32_t)(it & 1) * STAGE_BYTES + aoff;
            const uint32_t pB = smb + (uint32_t)(it & 1) * STAGE_BYTES + B_HI + boff;
            #pragma unroll
            for (int kk = 0; kk < 4; ++kk) {
                uint32_t bh[8], bl[8];
                LDSM4(bh[0], bh[1], bh[2], bh[3], pB + kk*32);
                LDSM4(bh[4], bh[5], bh[6], bh[7], pB + 16*RSB + kk*32);
                LDSM4(bl[0], bl[1], bl[2], bl[3], pB + (B_LO - B_HI) + kk*32);
                LDSM4(bl[4], bl[5], bl[6], bl[7], pB + (B_LO - B_HI) + 16*RSB + kk*32);
                uint32_t ah[4][4], al[4][4];
                #pragma unroll
                for (int mf = 0; mf < 4; ++mf) {
                    LDSM4(ah[mf][0], ah[mf][1], ah[mf][2], ah[mf][3],
                          pA + mf*(16*RSB) + kk*32);
                    LDSM4(al[mf][0], al[mf][1], al[mf][2], al[mf][3],
                          pA + A_LO + mf*(16*RSB) + kk*32);
                }
                #pragma unroll
                for (int mf = 0; mf < 4; ++mf)
                    #pragma unroll
                    for (int f = 0; f < 4; ++f) {
                        const int bi = (f >> 1)*4 + (f & 1)*2;
                        MMA(acc[mf][f], ah[mf], bh[bi], bh[bi+1]);   // Ahi*Bhi
                    }
                #pragma unroll
                for (int mf = 0; mf < 4; ++mf)
                    #pragma unroll
                    for (int f = 0; f < 4; ++f) {
                        const int bi = (f >> 1)*4 + (f & 1)*2;
                        MMA(acc[mf][f], ah[mf], bl[bi], bl[bi+1]);   // Ahi*Blo
                    }
                #pragma unroll
                for (int mf = 0; mf < 4; ++mf)
                    #pragma unroll
                    for (int f = 0; f < 4; ++f) {
                        const int bi = (f >> 1)*4 + (f & 1)*2;
                        MMA(acc[mf][f], al[mf], bh[bi], bh[bi+1]);   // Alo*Bhi
                    }
            }
        }
    }

    // ---- epilogue: accumulators -> split-K scratch ----
    float* dst = g_scratch + ((size_t)ks << 18);
    #pragma unroll
    for (int mf = 0; mf < 4; ++mf) {
        const int r = m0 + wm*64 + mf*16 + (lane >> 2);
        #pragma unroll
        for (int f = 0; f < 4; ++f) {
            const int c = n0 + wn*32 + f*8 + (lane & 3)*2;
            float2 v0; v0.x = acc[mf][f][0]; v0.y = acc[mf][f][1];
            float2 v1; v1.x = acc[mf][f][2]; v1.y = acc[mf][f][3];
            *(float2*)(dst + (size_t)r * NO + c)       = v0;
            *(float2*)(dst + (size_t)(r + 8) * NO + c) = v1;
        }
    }
}

__global__ void __launch_bounds__(512, 1)
fkan_reduce(const float* __restrict__ bias, float* __restrict__ out)
{
    const int idx = blockIdx.x * 512 + threadIdx.x;
    float a = bias[idx & 255];
    #pragma unroll
    for (int k = 0; k < SPLITK; ++k)
        a += g_scratch[((size_t)k << 18) + idx];
    out[idx] = a;
}

// pad kernel: shifts launch-pattern period to 4 so ncu -s 5 profiles fkan_hmma
__global__ void fkan_pad() {}

extern "C" void kernel_launch(void* const* d_in, const int* in_sizes, int n_in,
                              void* d_out, int out_size) {
    const float* x    = (const float*)d_in[0];
    const float* fc   = (const float*)d_in[1];
    const float* bias = (const float*)d_in[2];
    float* out        = (float*)d_out;

    cudaFuncSetAttribute(fkan_hmma, cudaFuncAttributeMaxDynamicSharedMemorySize, DYN_SMEM);
    fkan_conv<<<40960, 512>>>(fc);
    fkan_hmma<<<dim3(SPLITK, 8, 2), 256, DYN_SMEM>>>(x);
    fkan_reduce<<<512, 512>>>(bias, out);
    fkan_pad<<<1, 32>>>();
}